// round 6
// baseline (speedup 1.0000x reference)
#include <cuda_runtime.h>
#include <stdint.h>

// ---------------- problem constants ----------------
#define TOTAL   488418
#define NELEM   4884180          // 10 * TOTAL
#define NSETS   80               // 8 slices * 10 batch rows
#define NBINS   65536
#define TIECAP  16384

__constant__ int c_base[8]  = {0,160000,160400,320400,320800,480800,481200,488400};
__constant__ int c_ns[8]    = {160000,400,160000,400,160000,400,7200,18};
__constant__ int c_k[8]     = {80000,200,80000,200,80000,200,3600,9};
__constant__ int c_obase[8] = {0,1600000,1604000,3204000,3208000,4808000,4812000,4884000};

// ---------------- scratch (static device memory; no runtime alloc) ----------------
__device__ uint32_t g_keys[NELEM];           // 19.5 MB: order-preserving keys of mv+g
__device__ uint32_t g_hist1[NSETS * NBINS];  // 21 MB
__device__ uint32_t g_hist2[NSETS * NBINS];  // 21 MB
__device__ float    g_h[10 * 256];
__device__ uint32_t g_prefix[NSETS];
__device__ uint32_t g_rem[NSETS];
__device__ uint32_t g_T[NSETS];              // exact 32-bit threshold key (k-th largest)
__device__ uint32_t g_tneed[NSETS];          // how many of the ==T elements to take
__device__ uint32_t g_tc[NSETS];             // tie counts
__device__ uint32_t g_tlist[NSETS * TIECAP]; // out-indices of ==T elements

// ---------------- helpers ----------------
__device__ __forceinline__ int slice_of(int col) {
    if (col < 160000) return 0;
    if (col < 160400) return 1;
    if (col < 320400) return 2;
    if (col < 320800) return 3;
    if (col < 480800) return 4;
    if (col < 481200) return 5;
    if (col < 488400) return 6;
    return 7;
}

// JAX threefry2x32, 20 rounds, key = (0, 42)
__device__ __forceinline__ void threefry_0_42(uint32_t c0, uint32_t c1,
                                              uint32_t& o0, uint32_t& o1) {
    const uint32_t ks0 = 0u, ks1 = 42u, ks2 = 0x1BD11BDAu ^ 42u;
    uint32_t x0 = c0 + ks0;
    uint32_t x1 = c1 + ks1;
#define TF_R(r) { x0 += x1; x1 = (x1 << (r)) | (x1 >> (32 - (r))); x1 ^= x0; }
    TF_R(13) TF_R(15) TF_R(26) TF_R(6)
    x0 += ks1; x1 += ks2 + 1u;
    TF_R(17) TF_R(29) TF_R(16) TF_R(24)
    x0 += ks2; x1 += ks0 + 2u;
    TF_R(13) TF_R(15) TF_R(26) TF_R(6)
    x0 += ks0; x1 += ks1 + 3u;
    TF_R(17) TF_R(29) TF_R(16) TF_R(24)
    x0 += ks1; x1 += ks2 + 4u;
    TF_R(13) TF_R(15) TF_R(26) TF_R(6)
    x0 += ks2; x1 += ks0 + 5u;
#undef TF_R
    o0 = x0; o1 = x1;
}

// JAX partitionable threefry (default since JAX 0.5): per-element 64-bit
// counter (hi=0 here since NELEM < 2^32); 32-bit bits = o0 ^ o1.
__device__ __forceinline__ uint32_t jax_bits(uint32_t p) {
    uint32_t o0, o1;
    threefry_0_42(0u, p, o0, o1);
    return o0 ^ o1;
}

__device__ __forceinline__ float jax_gumbel(uint32_t bits) {
    float f = __uint_as_float((bits >> 9) | 0x3f800000u) - 1.0f;
    float u = fmaxf(f, 1.17549435e-38f);          // minval = tiny
    float l = logf(u);                             // fp32, like ref
    return -logf(-l);
}

__device__ __forceinline__ uint32_t ordkey(float v) {
    uint32_t b = __float_as_uint(v);
    return (b & 0x80000000u) ? ~b : (b | 0x80000000u);  // ascending order map
}

// ---------------- K0: clear histograms + tie counters ----------------
__global__ void k0_clear() {
    int n = NSETS * NBINS;
    for (int i = blockIdx.x * blockDim.x + threadIdx.x; i < n; i += gridDim.x * blockDim.x) {
        g_hist1[i] = 0u; g_hist2[i] = 0u;
    }
    if (blockIdx.x == 0 && threadIdx.x < NSETS) g_tc[threadIdx.x] = 0u;
}

// ---------------- K1: h = relu(emb @ W1 + b1)  [10,256] ----------------
__global__ void k1_hidden(const float* __restrict__ emb, const float* __restrict__ W1,
                          const float* __restrict__ b1) {
    __shared__ float se[100];
    if (threadIdx.x < 100) se[threadIdx.x] = emb[threadIdx.x];
    __syncthreads();
    int t = threadIdx.x;           // hidden unit, 256 threads
    float bb = b1[t];
    #pragma unroll
    for (int b = 0; b < 10; b++) {
        float a = 0.0f;
        #pragma unroll
        for (int i = 0; i < 10; i++) a = fmaf(se[b * 10 + i], W1[i * 256 + t], a);
        a += bb;
        g_h[b * 256 + t] = fmaxf(a, 0.0f);
    }
}

// ---------------- K2: GEMV + gumbel + keys + pass-1 histogram ----------------
__global__ void __launch_bounds__(256) k2_main(const float* __restrict__ W2,
                                               const float* __restrict__ b2) {
    __shared__ float sh[2560];
    for (int i = threadIdx.x; i < 2560; i += 256) sh[i] = g_h[i];
    __syncthreads();

    int col = blockIdx.x * 256 + threadIdx.x;
    if (col >= TOTAL) return;

    float acc[10];
    #pragma unroll
    for (int b = 0; b < 10; b++) acc[b] = 0.0f;

    const float* wp = W2 + col;
    #pragma unroll 4
    for (int kk = 0; kk < 256; kk++) {
        float w = __ldg(wp + kk * TOTAL);
        #pragma unroll
        for (int b = 0; b < 10; b++) acc[b] = fmaf(sh[b * 256 + kk], w, acc[b]);
    }

    float b2c = __ldg(b2 + col);
    int s = slice_of(col);
    #pragma unroll
    for (int b = 0; b < 10; b++) {
        uint32_t p = (uint32_t)b * TOTAL + (uint32_t)col;
        float g = jax_gumbel(jax_bits(p));
        float v = (acc[b] + b2c) + g;
        uint32_t key = ordkey(v);
        g_keys[p] = key;
        atomicAdd(&g_hist1[(s * 10 + b) * NBINS + (key >> 16)], 1u);
    }
}

// ---------------- radix scan (descending) shared by K3/K5 ----------------
__device__ __forceinline__ void scan_desc(const uint32_t* __restrict__ h, uint32_t need,
                                          uint32_t* out_bin, uint32_t* out_rem) {
    __shared__ uint32_t csum[256];
    __shared__ uint32_t above_s[256];
    int tid = threadIdx.x;
    uint32_t mysum = 0;
    #pragma unroll 8
    for (int i = 0; i < 256; i++) mysum += h[tid * 256 + i];
    csum[tid] = mysum;
    __syncthreads();
    if (tid == 0) {
        uint32_t a = 0;
        for (int i = 255; i >= 0; i--) { above_s[i] = a; a += csum[i]; }
    }
    __syncthreads();
    uint32_t above = above_s[tid];
    if (above < need && above + csum[tid] >= need) {
        uint32_t a = above;
        for (int i = 255; i >= 0; i--) {
            uint32_t c = h[tid * 256 + i];
            if (a + c >= need) { *out_bin = (uint32_t)(tid * 256 + i); *out_rem = need - a; break; }
            a += c;
        }
    }
}

// ---------------- K3: pass-1 scan -> prefix + remaining ----------------
__global__ void k3_scan1() {
    int set = blockIdx.x;
    uint32_t need = (uint32_t)c_k[set / 10];
    __shared__ uint32_t bin, rem;
    scan_desc(g_hist1 + (size_t)set * NBINS, need, &bin, &rem);
    __syncthreads();
    if (threadIdx.x == 0) { g_prefix[set] = bin; g_rem[set] = rem; }
}

// ---------------- K4: pass-2 histogram of low 16 bits within prefix ----------------
__global__ void k4_hist2() {
    __shared__ uint32_t spfx[NSETS];
    if (threadIdx.x < NSETS) spfx[threadIdx.x] = g_prefix[threadIdx.x];
    __syncthreads();
    int col = blockIdx.x * 256 + threadIdx.x;
    if (col >= TOTAL) return;
    int s = slice_of(col);
    #pragma unroll
    for (int b = 0; b < 10; b++) {
        uint32_t key = g_keys[(uint32_t)b * TOTAL + (uint32_t)col];
        int set = s * 10 + b;
        if ((key >> 16) == spfx[set])
            atomicAdd(&g_hist2[(size_t)set * NBINS + (key & 0xFFFFu)], 1u);
    }
}

// ---------------- K5: pass-2 scan -> exact threshold key + tie quota ----------------
__global__ void k5_scan2() {
    int set = blockIdx.x;
    uint32_t need = g_rem[set];
    __shared__ uint32_t bin, rem;
    scan_desc(g_hist2 + (size_t)set * NBINS, need, &bin, &rem);
    __syncthreads();
    if (threadIdx.x == 0) {
        g_T[set] = (g_prefix[set] << 16) | bin;
        g_tneed[set] = rem;   // 1 <= rem <= count(==T)
    }
}

// ---------------- K6: emit 0/1 and collect ties ----------------
__global__ void k6_emit(float* __restrict__ out) {
    __shared__ uint32_t sT[NSETS];
    if (threadIdx.x < NSETS) sT[threadIdx.x] = g_T[threadIdx.x];
    __syncthreads();
    int col = blockIdx.x * 256 + threadIdx.x;
    if (col >= TOTAL) return;
    int s = slice_of(col);
    int j = col - c_base[s];
    int ob = c_obase[s];
    int ns = c_ns[s];
    #pragma unroll
    for (int b = 0; b < 10; b++) {
        int set = s * 10 + b;
        uint32_t key = g_keys[(uint32_t)b * TOTAL + (uint32_t)col];
        uint32_t T = sT[set];
        int oo = ob + b * ns + j;
        out[oo] = (key > T) ? 1.0f : 0.0f;
        if (key == T) {
            uint32_t idx = atomicAdd(&g_tc[set], 1u);
            if (idx < TIECAP) g_tlist[(size_t)set * TIECAP + idx] = (uint32_t)oo;
        }
    }
}

// ---------------- K7: resolve ties by smallest output index (== lax.top_k order) ----
__global__ void k7_ties(float* __restrict__ out) {
    int set = blockIdx.x;
    uint32_t E = g_tc[set]; if (E > TIECAP) E = TIECAP;
    uint32_t t = g_tneed[set];
    const uint32_t* lst = g_tlist + (size_t)set * TIECAP;
    for (uint32_t i = threadIdx.x; i < E; i += blockDim.x) {
        uint32_t oo = lst[i];
        if (t >= E) { out[oo] = 1.0f; continue; }
        uint32_t rank = 0;
        for (uint32_t jj = 0; jj < E; jj++) rank += (lst[jj] < oo) ? 1u : 0u;
        if (rank < t) out[oo] = 1.0f;
    }
}

// ---------------- launch ----------------
extern "C" void kernel_launch(void* const* d_in, const int* in_sizes, int n_in,
                              void* d_out, int out_size) {
    // inputs (metadata order): x, embedding_input, W1, b1, W2, b2
    const float* emb = (const float*)d_in[1];
    const float* W1  = (const float*)d_in[2];
    const float* b1  = (const float*)d_in[3];
    const float* W2  = (const float*)d_in[4];
    const float* b2  = (const float*)d_in[5];
    float* out = (float*)d_out;

    const int CB = (TOTAL + 255) / 256;   // 1908 column blocks

    k0_clear<<<512, 256>>>();
    k1_hidden<<<1, 256>>>(emb, W1, b1);
    k2_main<<<CB, 256>>>(W2, b2);
    k3_scan1<<<NSETS, 256>>>();
    k4_hist2<<<CB, 256>>>();
    k5_scan2<<<NSETS, 256>>>();
    k6_emit<<<CB, 256>>>(out);
    k7_ties<<<NSETS, 256>>>(out);
}

// round 10
// speedup vs baseline: 1.3983x; 1.3983x over previous
#include <cuda_runtime.h>
#include <stdint.h>

// ---------------- problem constants ----------------
#define TOTAL   488418
#define NPAIR   244209           // TOTAL/2
#define NELEM   4884180          // 10 * TOTAL
#define NSETS   80               // 8 slices * 10 batch rows
#define NBINS   65536
#define NCHUNK  64               // 1024 bins per chunk
#define TIECAP  16384
#define CANDCAP 32768

__constant__ int c_base[8]  = {0,160000,160400,320400,320800,480800,481200,488400};
__constant__ int c_ns[8]    = {160000,400,160000,400,160000,400,7200,18};
__constant__ int c_k[8]     = {80000,200,80000,200,80000,200,3600,9};
__constant__ int c_obase[8] = {0,1600000,1604000,3204000,3208000,4808000,4812000,4884000};

// ---------------- scratch (static device memory; no runtime alloc) ----------------
__device__ uint32_t g_keys[NELEM];            // 19.5 MB
__device__ uint32_t g_hist1[NSETS * NBINS];   // 21 MB
__device__ uint32_t g_part[NSETS * NCHUNK];   // chunk partial sums
__device__ float    g_h[10 * 256];
__device__ uint32_t g_prefix[NSETS];
__device__ uint32_t g_rem[NSETS];
__device__ uint32_t g_T[NSETS];
__device__ uint32_t g_tneed[NSETS];
__device__ uint32_t g_tc[NSETS];
__device__ uint32_t g_cc[NSETS];                       // candidate counts
__device__ uint16_t g_cand[NSETS * CANDCAP];           // low16 of in-bin keys
__device__ uint32_t g_tlist[NSETS * TIECAP];

// ---------------- helpers ----------------
__device__ __forceinline__ int slice_of(int col) {
    if (col < 160000) return 0;
    if (col < 160400) return 1;
    if (col < 320400) return 2;
    if (col < 320800) return 3;
    if (col < 480800) return 4;
    if (col < 481200) return 5;
    if (col < 488400) return 6;
    return 7;
}

// JAX threefry2x32, 20 rounds, key = (0, 42)
__device__ __forceinline__ void threefry_0_42(uint32_t c0, uint32_t c1,
                                              uint32_t& o0, uint32_t& o1) {
    const uint32_t ks0 = 0u, ks1 = 42u, ks2 = 0x1BD11BDAu ^ 42u;
    uint32_t x0 = c0 + ks0;
    uint32_t x1 = c1 + ks1;
#define TF_R(r) { x0 += x1; x1 = (x1 << (r)) | (x1 >> (32 - (r))); x1 ^= x0; }
    TF_R(13) TF_R(15) TF_R(26) TF_R(6)
    x0 += ks1; x1 += ks2 + 1u;
    TF_R(17) TF_R(29) TF_R(16) TF_R(24)
    x0 += ks2; x1 += ks0 + 2u;
    TF_R(13) TF_R(15) TF_R(26) TF_R(6)
    x0 += ks0; x1 += ks1 + 3u;
    TF_R(17) TF_R(29) TF_R(16) TF_R(24)
    x0 += ks1; x1 += ks2 + 4u;
    TF_R(13) TF_R(15) TF_R(26) TF_R(6)
    x0 += ks2; x1 += ks0 + 5u;
#undef TF_R
    o0 = x0; o1 = x1;
}

// JAX partitionable threefry: counter (0, p), bits = o0 ^ o1
__device__ __forceinline__ uint32_t jax_bits(uint32_t p) {
    uint32_t o0, o1;
    threefry_0_42(0u, p, o0, o1);
    return o0 ^ o1;
}

__device__ __forceinline__ float jax_gumbel(uint32_t bits) {
    float f = __uint_as_float((bits >> 9) | 0x3f800000u) - 1.0f;
    float u = fmaxf(f, 1.17549435e-38f);
    float l = logf(u);
    return -logf(-l);
}

__device__ __forceinline__ uint32_t ordkey(float v) {
    uint32_t b = __float_as_uint(v);
    return (b & 0x80000000u) ? ~b : (b | 0x80000000u);
}

// ---------------- K0: vectorized clear of hist1 + counters ----------------
__global__ void k0_clear() {
    const int n4 = NSETS * NBINS / 4;           // uint4 count
    uint4* h4 = reinterpret_cast<uint4*>(g_hist1);
    uint4 z = make_uint4(0u, 0u, 0u, 0u);
    for (int i = blockIdx.x * blockDim.x + threadIdx.x; i < n4; i += gridDim.x * blockDim.x)
        h4[i] = z;
    if (blockIdx.x == 0 && threadIdx.x < NSETS) {
        g_tc[threadIdx.x] = 0u;
        g_cc[threadIdx.x] = 0u;
    }
}

// ---------------- K1: h = relu(emb @ W1 + b1)  [10,256] ----------------
__global__ void k1_hidden(const float* __restrict__ emb, const float* __restrict__ W1,
                          const float* __restrict__ b1) {
    __shared__ float se[100];
    if (threadIdx.x < 100) se[threadIdx.x] = emb[threadIdx.x];
    __syncthreads();
    int t = threadIdx.x;
    float bb = b1[t];
    #pragma unroll
    for (int b = 0; b < 10; b++) {
        float a = 0.0f;
        #pragma unroll
        for (int i = 0; i < 10; i++) a = fmaf(se[b * 10 + i], W1[i * 256 + t], a);
        a += bb;
        g_h[b * 256 + t] = fmaxf(a, 0.0f);
    }
}

// ---------------- K2: float2 GEMV + gumbel + keys + pass-1 histogram ----------------
// Per-column accumulation order identical to the validated scalar version
// (kk = 0..255 sequential fmaf) -> bitwise-identical keys.
__global__ void __launch_bounds__(256) k2_main(const float* __restrict__ W2,
                                               const float* __restrict__ b2) {
    __shared__ float sh[2560];
    for (int i = threadIdx.x; i < 2560; i += 256) sh[i] = g_h[i];
    __syncthreads();

    int pair = blockIdx.x * 256 + threadIdx.x;
    if (pair >= NPAIR) return;
    int col = pair * 2;

    float acc0[10], acc1[10];
    #pragma unroll
    for (int b = 0; b < 10; b++) { acc0[b] = 0.0f; acc1[b] = 0.0f; }

    const float2* wp = reinterpret_cast<const float2*>(W2) + pair;  // 8B aligned (TOTAL even)
    #pragma unroll 8
    for (int kk = 0; kk < 256; kk++) {
        float2 w = __ldg(wp + (size_t)kk * NPAIR);
        #pragma unroll
        for (int b = 0; b < 10; b++) {
            float hv = sh[b * 256 + kk];
            acc0[b] = fmaf(hv, w.x, acc0[b]);
            acc1[b] = fmaf(hv, w.y, acc1[b]);
        }
    }

    float2 b2c = __ldg(reinterpret_cast<const float2*>(b2) + pair);
    int s0 = slice_of(col);
    int s1 = slice_of(col + 1);
    #pragma unroll
    for (int b = 0; b < 10; b++) {
        uint32_t p = (uint32_t)b * TOTAL + (uint32_t)col;
        float v0 = (acc0[b] + b2c.x) + jax_gumbel(jax_bits(p));
        float v1 = (acc1[b] + b2c.y) + jax_gumbel(jax_bits(p + 1u));
        uint32_t k0 = ordkey(v0), k1 = ordkey(v1);
        *reinterpret_cast<uint2*>(&g_keys[p]) = make_uint2(k0, k1);  // p even -> 8B aligned
        atomicAdd(&g_hist1[(s0 * 10 + b) * NBINS + (k0 >> 16)], 1u);
        atomicAdd(&g_hist1[(s1 * 10 + b) * NBINS + (k1 >> 16)], 1u);
    }
}

// ---------------- K3a: coalesced chunk partial sums (grid = 64 x 80) ----------------
__global__ void k3a_partial() {
    int chunk = blockIdx.x;       // 0..63
    int set   = blockIdx.y;       // 0..79
    int tid   = threadIdx.x;      // 256 threads, 4 bins each via uint4
    const uint4* h4 = reinterpret_cast<const uint4*>(
        g_hist1 + (size_t)set * NBINS + chunk * 1024);
    uint4 v = h4[tid];
    uint32_t s = v.x + v.y + v.z + v.w;
    __shared__ uint32_t red[256];
    red[tid] = s;
    __syncthreads();
    for (int off = 128; off > 0; off >>= 1) {
        if (tid < off) red[tid] += red[tid + off];
        __syncthreads();
    }
    if (tid == 0) g_part[set * NCHUNK + chunk] = red[0];
}

// ---------------- K3b: find prefix bin + rem (descending), all in shared ----------
__global__ void k3b_find() {
    int set = blockIdx.x;
    int tid = threadIdx.x;
    uint32_t need = (uint32_t)c_k[set / 10];

    __shared__ uint32_t sch[NCHUNK];
    __shared__ uint32_t sC, sR1;
    if (tid < NCHUNK) sch[tid] = g_part[set * NCHUNK + tid];
    __syncthreads();
    if (tid == 0) {
        uint32_t a = 0;
        for (int c = NCHUNK - 1; c >= 0; c--) {
            if (a + sch[c] >= need) { sC = (uint32_t)c; sR1 = need - a; break; }
            a += sch[c];
        }
    }
    __syncthreads();

    __shared__ uint32_t sbin[1024];
    const uint32_t* hb = g_hist1 + (size_t)set * NBINS + sC * 1024;
    for (int i = tid; i < 1024; i += 256) sbin[i] = hb[i];
    __syncthreads();

    __shared__ uint32_t sub[256];
    sub[tid] = sbin[tid * 4] + sbin[tid * 4 + 1] + sbin[tid * 4 + 2] + sbin[tid * 4 + 3];
    __syncthreads();

    if (tid == 0) {
        uint32_t a = 0; uint32_t S = 0, r2 = 0;
        for (int c = 255; c >= 0; c--) {
            if (a + sub[c] >= sR1) { S = (uint32_t)c; r2 = sR1 - a; break; }
            a += sub[c];
        }
        uint32_t a2 = 0;
        for (int i = 3; i >= 0; i--) {
            uint32_t cc = sbin[S * 4 + i];
            if (a2 + cc >= r2) {
                g_prefix[set] = sC * 1024 + S * 4 + (uint32_t)i;
                g_rem[set]    = r2 - a2;
                break;
            }
            a2 += cc;
        }
    }
}

// ---------------- K4: compact candidates (keys in the prefix bin) ----------------
__global__ void k4_compact() {
    __shared__ uint32_t spfx[NSETS];
    if (threadIdx.x < NSETS) spfx[threadIdx.x] = g_prefix[threadIdx.x];
    __syncthreads();
    int col = blockIdx.x * 256 + threadIdx.x;
    if (col >= TOTAL) return;
    int s = slice_of(col);
    #pragma unroll
    for (int b = 0; b < 10; b++) {
        uint32_t key = g_keys[(uint32_t)b * TOTAL + (uint32_t)col];
        int set = s * 10 + b;
        if ((key >> 16) == spfx[set]) {
            uint32_t idx = atomicAdd(&g_cc[set], 1u);
            if (idx < CANDCAP)
                g_cand[(size_t)set * CANDCAP + idx] = (uint16_t)(key & 0xFFFFu);
        }
    }
}

// ---------------- K5: exact select on candidate list (two byte-level passes) -----
__global__ void k5_select() {
    int set = blockIdx.x;
    int tid = threadIdx.x;
    uint32_t cnt = g_cc[set]; if (cnt > CANDCAP) cnt = CANDCAP;
    uint32_t need = g_rem[set];
    const uint16_t* lst = g_cand + (size_t)set * CANDCAP;

    __shared__ uint32_t hist[256];
    __shared__ uint32_t sH, sR2;
    hist[tid] = 0u;
    __syncthreads();
    for (uint32_t i = tid; i < cnt; i += 256)
        atomicAdd(&hist[lst[i] >> 8], 1u);
    __syncthreads();
    if (tid == 0) {
        uint32_t a = 0;
        for (int c = 255; c >= 0; c--) {
            if (a + hist[c] >= need) { sH = (uint32_t)c; sR2 = need - a; break; }
            a += hist[c];
        }
    }
    __syncthreads();
    hist[tid] = 0u;
    __syncthreads();
    for (uint32_t i = tid; i < cnt; i += 256) {
        uint32_t v = lst[i];
        if ((v >> 8) == sH) atomicAdd(&hist[v & 0xFFu], 1u);
    }
    __syncthreads();
    if (tid == 0) {
        uint32_t a = 0;
        for (int c = 255; c >= 0; c--) {
            if (a + hist[c] >= sR2) {
                g_T[set]     = (g_prefix[set] << 16) | (sH << 8) | (uint32_t)c;
                g_tneed[set] = sR2 - a;
                break;
            }
            a += hist[c];
        }
    }
}

// ---------------- K6: emit 0/1 and collect ties ----------------
__global__ void k6_emit(float* __restrict__ out) {
    __shared__ uint32_t sT[NSETS];
    if (threadIdx.x < NSETS) sT[threadIdx.x] = g_T[threadIdx.x];
    __syncthreads();
    int col = blockIdx.x * 256 + threadIdx.x;
    if (col >= TOTAL) return;
    int s = slice_of(col);
    int j = col - c_base[s];
    int ob = c_obase[s];
    int ns = c_ns[s];
    #pragma unroll
    for (int b = 0; b < 10; b++) {
        int set = s * 10 + b;
        uint32_t key = g_keys[(uint32_t)b * TOTAL + (uint32_t)col];
        uint32_t T = sT[set];
        int oo = ob + b * ns + j;
        out[oo] = (key > T) ? 1.0f : 0.0f;
        if (key == T) {
            uint32_t idx = atomicAdd(&g_tc[set], 1u);
            if (idx < TIECAP) g_tlist[(size_t)set * TIECAP + idx] = (uint32_t)oo;
        }
    }
}

// ---------------- K7: resolve ties by smallest output index ----------------
__global__ void k7_ties(float* __restrict__ out) {
    int set = blockIdx.x;
    uint32_t E = g_tc[set]; if (E > TIECAP) E = TIECAP;
    uint32_t t = g_tneed[set];
    const uint32_t* lst = g_tlist + (size_t)set * TIECAP;
    for (uint32_t i = threadIdx.x; i < E; i += blockDim.x) {
        uint32_t oo = lst[i];
        if (t >= E) { out[oo] = 1.0f; continue; }
        uint32_t rank = 0;
        for (uint32_t jj = 0; jj < E; jj++) rank += (lst[jj] < oo) ? 1u : 0u;
        if (rank < t) out[oo] = 1.0f;
    }
}

// ---------------- launch ----------------
extern "C" void kernel_launch(void* const* d_in, const int* in_sizes, int n_in,
                              void* d_out, int out_size) {
    // inputs (metadata order): x, embedding_input, W1, b1, W2, b2
    const float* emb = (const float*)d_in[1];
    const float* W1  = (const float*)d_in[2];
    const float* b1  = (const float*)d_in[3];
    const float* W2  = (const float*)d_in[4];
    const float* b2  = (const float*)d_in[5];
    float* out = (float*)d_out;

    const int CB = (TOTAL + 255) / 256;     // 1908 column blocks
    const int PB = (NPAIR + 255) / 256;     // 954 pair blocks

    k0_clear<<<1024, 256>>>();
    k1_hidden<<<1, 256>>>(emb, W1, b1);
    k2_main<<<PB, 256>>>(W2, b2);
    k3a_partial<<<dim3(NCHUNK, NSETS), 256>>>();
    k3b_find<<<NSETS, 256>>>();
    k4_compact<<<CB, 256>>>();
    k5_select<<<NSETS, 256>>>();
    k6_emit<<<CB, 256>>>(out);
    k7_ties<<<NSETS, 256>>>(out);
}